// round 11
// baseline (speedup 1.0000x reference)
#include <cuda_runtime.h>
#include <math_constants.h>

// CrumbReconstructor: per 8-float block of x, argmin over 256 codebook rows of
// squared L2, emit the winning row.
//
// score(j) = ||m_j||^2 - 2*k.m_j   (||k||^2 dropped: uniform in j).
// f32x2 pairs TWO CODES (j, j+1) per lane-pair; 8 FFMA2 per code pair.
// Hierarchical argmin (R8): inner path = FFMA2 + FMNMX only; one guarded
// update per group of 8 codes; exact first-index recovered by bitwise-
// identical rescan of the winning group.
//
// R10: RF-bank fix. FFMA2 reads 3 register PAIRS -> 3 distinct even + 3
// distinct odd bank reads -> rt=3 (measured plateau 72us == 25.7M warp-FFMA2
// x3cyc/592). Interchange the inner loops (c outer, block p inner) so the
// warp-uniform code operand repeats across 4 consecutive FFMA2s and is
// served by the operand-reuse cache -> rt=2. Accumulation order per block
// stays c-ascending (bitwise identical to epilogue rescan).

#define MBLK   8
#define NCODES 256
#define NJP    (NCODES / 2)   // 128 code pairs
#define NGRP   (NJP / 4)      // 32 groups of 4 pairs (8 codes)
#define TPB    128
#define KPT    4              // key-blocks per thread

typedef unsigned long long u64;

__device__ __forceinline__ u64 pack2(float lo, float hi) {
    u64 r; asm("mov.b64 %0, {%1, %2};" : "=l"(r) : "f"(lo), "f"(hi)); return r;
}
__device__ __forceinline__ void unpack2(u64 v, float& lo, float& hi) {
    asm("mov.b64 {%0, %1}, %2;" : "=f"(lo), "=f"(hi) : "l"(v));
}
__device__ __forceinline__ u64 ffma2(u64 a, u64 b, u64 c) {
    u64 d; asm("fma.rn.f32x2 %0, %1, %2, %3;" : "=l"(d) : "l"(a), "l"(b), "l"(c));
    return d;
}

__global__ __launch_bounds__(TPB, 4)
void crumb_kernel(const float* __restrict__ x,
                  const float* __restrict__ mem,
                  float* __restrict__ out,
                  int nblocks)
{
    // Pair-interleaved codebook, row jp (80B stride, 16B aligned):
    //   u64[c] = (-2*m[2jp][c], -2*m[2jp+1][c])  c=0..7
    //   u64[8] = (||m_2jp||^2, ||m_2jp+1||^2)
    __shared__ __align__(16) u64 spair[NJP][10];
    __shared__ float4 sOrig[NCODES][2];

    const int tid = threadIdx.x;

    // ---- setup: scatter codebook into pair-interleaved layout ----
    for (int j = tid; j < NCODES; j += TPB) {
        const float4* m4 = reinterpret_cast<const float4*>(mem);
        float4 a = m4[j * 2 + 0];
        float4 b = m4[j * 2 + 1];
        float mm = a.x*a.x + a.y*a.y + a.z*a.z + a.w*a.w
                 + b.x*b.x + b.y*b.y + b.z*b.z + b.w*b.w;
        float* sp = reinterpret_cast<float*>(&spair[j >> 1][0]);
        int h = j & 1;                    // lo half = even j (first index)
        sp[0*2 + h] = -2.f * a.x;
        sp[1*2 + h] = -2.f * a.y;
        sp[2*2 + h] = -2.f * a.z;
        sp[3*2 + h] = -2.f * a.w;
        sp[4*2 + h] = -2.f * b.x;
        sp[5*2 + h] = -2.f * b.y;
        sp[6*2 + h] = -2.f * b.z;
        sp[7*2 + h] = -2.f * b.w;
        sp[8*2 + h] = mm;
        sOrig[j][0] = a;
        sOrig[j][1] = b;
    }
    __syncthreads();

    const int base = blockIdx.x * (TPB * KPT);
    const float4* x4 = reinterpret_cast<const float4*>(x);

    u64   kp[KPT][8];              // dup-packed key components
    float gbest[KPT];              // global running min per block
    int   gidx[KPT];               // winning GROUP (8 codes) per block

    // ---- load keys (coalesced float4), duplicate into f32x2 halves ----
    #pragma unroll
    for (int p = 0; p < KPT; p++) {
        int b = base + p * TPB + tid;
        int bb = (b < nblocks) ? b : 0;
        float4 a = x4[(size_t)bb * 2 + 0];
        float4 v = x4[(size_t)bb * 2 + 1];
        kp[p][0] = pack2(a.x, a.x);
        kp[p][1] = pack2(a.y, a.y);
        kp[p][2] = pack2(a.z, a.z);
        kp[p][3] = pack2(a.w, a.w);
        kp[p][4] = pack2(v.x, v.x);
        kp[p][5] = pack2(v.y, v.y);
        kp[p][6] = pack2(v.z, v.z);
        kp[p][7] = pack2(v.w, v.w);
        gbest[p] = CUDART_INF_F;
        gidx[p]  = 0;
    }

    // ---- scan groups of 4 pairs: c-outer / p-inner so the uniform code
    //      operand repeats across consecutive FFMA2s (reuse cache, rt 3->2) ----
    #pragma unroll 2
    for (int g = 0; g < NGRP; g++) {
        float t[KPT];                      // group-running min per block
        #pragma unroll
        for (int q = 0; q < 4; q++) {
            const int jp = g * 4 + q;
            const ulonglong2* row = reinterpret_cast<const ulonglong2*>(&spair[jp][0]);
            ulonglong2 q0 = row[0];
            ulonglong2 q1 = row[1];
            ulonglong2 q2 = row[2];
            ulonglong2 q3 = row[3];
            u64 mmp = spair[jp][8];

            u64 d[KPT];
            #pragma unroll
            for (int p = 0; p < KPT; p++) d[p] = mmp;   // seed = (mm_j, mm_j+1)
            #pragma unroll
            for (int p = 0; p < KPT; p++) d[p] = ffma2(kp[p][0], q0.x, d[p]);
            #pragma unroll
            for (int p = 0; p < KPT; p++) d[p] = ffma2(kp[p][1], q0.y, d[p]);
            #pragma unroll
            for (int p = 0; p < KPT; p++) d[p] = ffma2(kp[p][2], q1.x, d[p]);
            #pragma unroll
            for (int p = 0; p < KPT; p++) d[p] = ffma2(kp[p][3], q1.y, d[p]);
            #pragma unroll
            for (int p = 0; p < KPT; p++) d[p] = ffma2(kp[p][4], q2.x, d[p]);
            #pragma unroll
            for (int p = 0; p < KPT; p++) d[p] = ffma2(kp[p][5], q2.y, d[p]);
            #pragma unroll
            for (int p = 0; p < KPT; p++) d[p] = ffma2(kp[p][6], q3.x, d[p]);
            #pragma unroll
            for (int p = 0; p < KPT; p++) d[p] = ffma2(kp[p][7], q3.y, d[p]);

            #pragma unroll
            for (int p = 0; p < KPT; p++) {
                float dl, dh; unpack2(d[p], dl, dh);
                float m = fminf(dl, dh);
                t[p] = (q == 0) ? m : fminf(t[p], m);
            }
        }
        // one guarded update per group of 8 codes; strict < keeps first group
        #pragma unroll
        for (int p = 0; p < KPT; p++) {
            if (t[p] < gbest[p]) { gbest[p] = t[p]; gidx[p] = g; }
        }
    }

    // ---- per block: recover exact first index within the winning group
    //      (c-ascending accumulation: bitwise identical to main loop) ----
    float4* o4 = reinterpret_cast<float4*>(out);
    #pragma unroll
    for (int p = 0; p < KPT; p++) {
        int b = base + p * TPB + tid;
        if (b >= nblocks) continue;
        const int g = gidx[p];
        const float v = gbest[p];
        int jwin = 0;
        bool found = false;
        #pragma unroll
        for (int q = 0; q < 4; q++) {
            if (found) continue;
            const int jp = g * 4 + q;
            const ulonglong2* row = reinterpret_cast<const ulonglong2*>(&spair[jp][0]);
            ulonglong2 q0 = row[0];
            ulonglong2 q1 = row[1];
            ulonglong2 q2 = row[2];
            ulonglong2 q3 = row[3];
            u64 d = spair[jp][8];
            d = ffma2(kp[p][0], q0.x, d);
            d = ffma2(kp[p][1], q0.y, d);
            d = ffma2(kp[p][2], q1.x, d);
            d = ffma2(kp[p][3], q1.y, d);
            d = ffma2(kp[p][4], q2.x, d);
            d = ffma2(kp[p][5], q2.y, d);
            d = ffma2(kp[p][6], q3.x, d);
            d = ffma2(kp[p][7], q3.y, d);
            float dl, dh; unpack2(d, dl, dh);
            if (dl == v)      { jwin = (jp << 1);     found = true; }
            else if (dh == v) { jwin = (jp << 1) + 1; found = true; }
        }
        o4[(size_t)b * 2 + 0] = sOrig[jwin][0];
        o4[(size_t)b * 2 + 1] = sOrig[jwin][1];
    }
}

extern "C" void kernel_launch(void* const* d_in, const int* in_sizes, int n_in,
                              void* d_out, int out_size)
{
    const float* x   = (const float*)d_in[0];
    const float* mem = (const float*)d_in[1];
    float* out = (float*)d_out;

    int nblocks = in_sizes[0] / MBLK;                 // 802816
    int per_cta = TPB * KPT;                          // 512
    int grid = (nblocks + per_cta - 1) / per_cta;     // 1568

    crumb_kernel<<<grid, TPB>>>(x, mem, out, nblocks);
}

// round 12
// speedup vs baseline: 1.3853x; 1.3853x over previous
#include <cuda_runtime.h>
#include <math_constants.h>

// CrumbReconstructor: per 8-float block of x, argmin over 256 codebook rows of
// squared L2, emit the winning row.
//
// score(j) = ||m_j||^2 - 2*k.m_j   (||k||^2 dropped: uniform in j).
// f32x2 pairs TWO CODES (j, j+1) per lane-pair; 8 FFMA2 per code pair.
// Hierarchical argmin (R8): inner path = FFMA2 + FMNMX only; one guarded
// update per group of 8 codes; exact first-index recovered by bitwise-
// identical rescan of the winning group.
//
// R11: break the FFMA2 RF-bank ceiling (3 reg-pairs -> rt=3 -> 72us floor).
// The code operand is warp-uniform: move the pair-interleaved codebook to
// __constant__ memory so it loads via LDCU into UNIFORM registers; FFMA2
// with a UR multiplier reads only 2 RF pairs -> rt=2. Keys now carry the -2
// (dup(-2k)); products are bitwise identical to the previous form.
// Pipeline: prep kernel -> __device__ staging -> memcpyToSymbol -> main.

#define MBLK   8
#define NCODES 256
#define NJP    (NCODES / 2)   // 128 code pairs
#define NGRP   (NJP / 4)      // 32 groups of 4 pairs (8 codes)
#define TPB    128
#define KPT    4              // key-blocks per thread

typedef unsigned long long u64;

// Pair-interleaved codebook, row jp (9 u64 per pair):
//   u64[c] = (m[2jp][c], m[2jp+1][c])   c = 0..7
//   u64[8] = (||m_2jp||^2, ||m_2jp+1||^2)
__device__   u64 g_stage[NJP * 9];
__constant__ u64 c_pair[NJP * 9];

__device__ __forceinline__ u64 pack2(float lo, float hi) {
    u64 r; asm("mov.b64 %0, {%1, %2};" : "=l"(r) : "f"(lo), "f"(hi)); return r;
}
__device__ __forceinline__ void unpack2(u64 v, float& lo, float& hi) {
    asm("mov.b64 {%0, %1}, %2;" : "=f"(lo), "=f"(hi) : "l"(v));
}
__device__ __forceinline__ u64 ffma2(u64 a, u64 b, u64 c) {
    u64 d; asm("fma.rn.f32x2 %0, %1, %2, %3;" : "=l"(d) : "l"(a), "l"(b), "l"(c));
    return d;
}

// ---- prep: build pair-interleaved codebook in staging (1 CTA, 256 thr) ----
__global__ void crumb_prep(const float* __restrict__ mem)
{
    const int j  = threadIdx.x;       // code row 0..255
    const int jp = j >> 1;
    const int h  = j & 1;             // lo half = even j (first index)
    float* stg = reinterpret_cast<float*>(g_stage);
    float mm = 0.f;
    #pragma unroll
    for (int c = 0; c < 8; c++) {
        float v = mem[j * 8 + c];
        stg[(jp * 9 + c) * 2 + h] = v;
        mm += v * v;
    }
    stg[(jp * 9 + 8) * 2 + h] = mm;
}

__global__ __launch_bounds__(TPB, 4)
void crumb_kernel(const float* __restrict__ x,
                  const float* __restrict__ mem,
                  float* __restrict__ out,
                  int nblocks)
{
    __shared__ float4 sOrig[NCODES][2];

    const int tid = threadIdx.x;

    // ---- setup: original codebook rows in smem for the final gather ----
    for (int j = tid; j < NCODES; j += TPB) {
        const float4* m4 = reinterpret_cast<const float4*>(mem);
        sOrig[j][0] = m4[j * 2 + 0];
        sOrig[j][1] = m4[j * 2 + 1];
    }
    __syncthreads();

    const int base = blockIdx.x * (TPB * KPT);
    const float4* x4 = reinterpret_cast<const float4*>(x);

    u64   kp[KPT][8];              // dup(-2*k) key components
    float gbest[KPT];              // global running min per block
    int   gidx[KPT];               // winning GROUP (8 codes) per block

    // ---- load keys (coalesced float4), pack dup(-2k) ----
    #pragma unroll
    for (int p = 0; p < KPT; p++) {
        int b = base + p * TPB + tid;
        int bb = (b < nblocks) ? b : 0;
        float4 a = x4[(size_t)bb * 2 + 0];
        float4 v = x4[(size_t)bb * 2 + 1];
        kp[p][0] = pack2(-2.f*a.x, -2.f*a.x);
        kp[p][1] = pack2(-2.f*a.y, -2.f*a.y);
        kp[p][2] = pack2(-2.f*a.z, -2.f*a.z);
        kp[p][3] = pack2(-2.f*a.w, -2.f*a.w);
        kp[p][4] = pack2(-2.f*v.x, -2.f*v.x);
        kp[p][5] = pack2(-2.f*v.y, -2.f*v.y);
        kp[p][6] = pack2(-2.f*v.z, -2.f*v.z);
        kp[p][7] = pack2(-2.f*v.w, -2.f*v.w);
        gbest[p] = CUDART_INF_F;
        gidx[p]  = 0;
    }

    // ---- scan groups of 4 pairs: code operands arrive via LDCU (uniform
    //      registers); inner path is FFMA2 + FMNMX only ----
    #pragma unroll 2
    for (int g = 0; g < NGRP; g++) {
        float t[KPT];                      // group-running min per block
        #pragma unroll
        for (int q = 0; q < 4; q++) {
            const int jp  = g * 4 + q;
            const int off = jp * 9;
            u64 c0 = c_pair[off + 0];
            u64 c1 = c_pair[off + 1];
            u64 c2 = c_pair[off + 2];
            u64 c3 = c_pair[off + 3];
            u64 c4 = c_pair[off + 4];
            u64 c5 = c_pair[off + 5];
            u64 c6 = c_pair[off + 6];
            u64 c7 = c_pair[off + 7];
            u64 mmp = c_pair[off + 8];
            #pragma unroll
            for (int p = 0; p < KPT; p++) {
                u64 d = mmp;               // seed = (mm_j, mm_j+1)
                d = ffma2(kp[p][0], c0, d);
                d = ffma2(kp[p][1], c1, d);
                d = ffma2(kp[p][2], c2, d);
                d = ffma2(kp[p][3], c3, d);
                d = ffma2(kp[p][4], c4, d);
                d = ffma2(kp[p][5], c5, d);
                d = ffma2(kp[p][6], c6, d);
                d = ffma2(kp[p][7], c7, d);
                float dl, dh; unpack2(d, dl, dh);
                float m = fminf(dl, dh);
                t[p] = (q == 0) ? m : fminf(t[p], m);
            }
        }
        // one guarded update per group of 8 codes; strict < keeps first group
        #pragma unroll
        for (int p = 0; p < KPT; p++) {
            if (t[p] < gbest[p]) { gbest[p] = t[p]; gidx[p] = g; }
        }
    }

    // ---- per block: recover exact first index within the winning group
    //      (identical const reads + c-ascending chain: bitwise identical) ----
    float4* o4 = reinterpret_cast<float4*>(out);
    #pragma unroll
    for (int p = 0; p < KPT; p++) {
        int b = base + p * TPB + tid;
        if (b >= nblocks) continue;
        const int g = gidx[p];
        const float v = gbest[p];
        int jwin = 0;
        bool found = false;
        #pragma unroll
        for (int q = 0; q < 4; q++) {
            if (found) continue;
            const int jp  = g * 4 + q;
            const int off = jp * 9;
            u64 d = c_pair[off + 8];
            d = ffma2(kp[p][0], c_pair[off + 0], d);
            d = ffma2(kp[p][1], c_pair[off + 1], d);
            d = ffma2(kp[p][2], c_pair[off + 2], d);
            d = ffma2(kp[p][3], c_pair[off + 3], d);
            d = ffma2(kp[p][4], c_pair[off + 4], d);
            d = ffma2(kp[p][5], c_pair[off + 5], d);
            d = ffma2(kp[p][6], c_pair[off + 6], d);
            d = ffma2(kp[p][7], c_pair[off + 7], d);
            float dl, dh; unpack2(d, dl, dh);
            if (dl == v)      { jwin = (jp << 1);     found = true; }
            else if (dh == v) { jwin = (jp << 1) + 1; found = true; }
        }
        o4[(size_t)b * 2 + 0] = sOrig[jwin][0];
        o4[(size_t)b * 2 + 1] = sOrig[jwin][1];
    }
}

extern "C" void kernel_launch(void* const* d_in, const int* in_sizes, int n_in,
                              void* d_out, int out_size)
{
    const float* x   = (const float*)d_in[0];
    const float* mem = (const float*)d_in[1];
    float* out = (float*)d_out;

    int nblocks = in_sizes[0] / MBLK;                 // 802816
    int per_cta = TPB * KPT;                          // 512
    int grid = (nblocks + per_cta - 1) / per_cta;     // 1568

    // 1) build pair-interleaved codebook in __device__ staging
    crumb_prep<<<1, NCODES>>>(mem);

    // 2) DtoD copy staging -> __constant__ (graph memcpy-to-symbol node)
    void* stage_ptr = nullptr;
    cudaGetSymbolAddress(&stage_ptr, g_stage);
    cudaMemcpyToSymbolAsync(c_pair, stage_ptr, sizeof(u64) * NJP * 9, 0,
                            cudaMemcpyDeviceToDevice, 0);

    // 3) main kernel reads codebook via LDCU (uniform registers)
    crumb_kernel<<<grid, TPB>>>(x, mem, out, nblocks);
}

// round 13
// speedup vs baseline: 1.9054x; 1.3754x over previous
#include <cuda_runtime.h>
#include <math_constants.h>

// CrumbReconstructor: per 8-float block of x, argmin over 256 codebook rows of
// squared L2, emit the winning row.
//
// score(j) = ||m_j||^2 - 2*k.m_j   (||k||^2 dropped: uniform in j).
// f32x2 pairs TWO CODES (j, j+1); 8 FFMA2 per code pair. Hierarchical argmin
// (R8): FFMA2 + FMNMX inner path, one guarded update per 8 codes, exact
// first-index recovered by bitwise-identical rescan of the winning group.
//
// R12: software-pipeline the codebook LDS. R8's issue sat at 49.6% with the
// fma pipe only ~60% busy: each pair's 5 LDS (29-cyc lat) are consumed
// immediately by its FFMA2s. Roll a one-pair-ahead register buffer so pair
// jp+1's LDS issue before pair jp's math, giving every load ~40 slots of
// cover. Arithmetic identical to R8.

#define MBLK   8
#define NCODES 256
#define NJP    (NCODES / 2)   // 128 code pairs
#define TPB    128
#define KPT    4              // key-blocks per thread

typedef unsigned long long u64;

__device__ __forceinline__ u64 pack2(float lo, float hi) {
    u64 r; asm("mov.b64 %0, {%1, %2};" : "=l"(r) : "f"(lo), "f"(hi)); return r;
}
__device__ __forceinline__ void unpack2(u64 v, float& lo, float& hi) {
    asm("mov.b64 {%0, %1}, %2;" : "=f"(lo), "=f"(hi) : "l"(v));
}
__device__ __forceinline__ u64 ffma2(u64 a, u64 b, u64 c) {
    u64 d; asm("fma.rn.f32x2 %0, %1, %2, %3;" : "=l"(d) : "l"(a), "l"(b), "l"(c));
    return d;
}

__global__ __launch_bounds__(TPB, 4)
void crumb_kernel(const float* __restrict__ x,
                  const float* __restrict__ mem,
                  float* __restrict__ out,
                  int nblocks)
{
    // Pair-interleaved codebook, row jp (80B stride, 16B aligned):
    //   u64[c] = (-2*m[2jp][c], -2*m[2jp+1][c])  c=0..7
    //   u64[8] = (||m_2jp||^2, ||m_2jp+1||^2)
    __shared__ __align__(16) u64 spair[NJP][10];
    __shared__ float4 sOrig[NCODES][2];

    const int tid = threadIdx.x;

    // ---- setup: scatter codebook into pair-interleaved layout ----
    for (int j = tid; j < NCODES; j += TPB) {
        const float4* m4 = reinterpret_cast<const float4*>(mem);
        float4 a = m4[j * 2 + 0];
        float4 b = m4[j * 2 + 1];
        float mm = a.x*a.x + a.y*a.y + a.z*a.z + a.w*a.w
                 + b.x*b.x + b.y*b.y + b.z*b.z + b.w*b.w;
        float* sp = reinterpret_cast<float*>(&spair[j >> 1][0]);
        int h = j & 1;                    // lo half = even j (first index)
        sp[0*2 + h] = -2.f * a.x;
        sp[1*2 + h] = -2.f * a.y;
        sp[2*2 + h] = -2.f * a.z;
        sp[3*2 + h] = -2.f * a.w;
        sp[4*2 + h] = -2.f * b.x;
        sp[5*2 + h] = -2.f * b.y;
        sp[6*2 + h] = -2.f * b.z;
        sp[7*2 + h] = -2.f * b.w;
        sp[8*2 + h] = mm;
        sOrig[j][0] = a;
        sOrig[j][1] = b;
    }
    __syncthreads();

    const int base = blockIdx.x * (TPB * KPT);
    const float4* x4 = reinterpret_cast<const float4*>(x);

    u64   kp[KPT][8];              // dup-packed key components
    float gbest[KPT];              // global running min per block
    int   gidx[KPT];               // winning GROUP (8 codes) per block
    float t[KPT];                  // group-running min

    // ---- load keys (coalesced float4), duplicate into f32x2 halves ----
    #pragma unroll
    for (int p = 0; p < KPT; p++) {
        int b = base + p * TPB + tid;
        int bb = (b < nblocks) ? b : 0;
        float4 a = x4[(size_t)bb * 2 + 0];
        float4 v = x4[(size_t)bb * 2 + 1];
        kp[p][0] = pack2(a.x, a.x);
        kp[p][1] = pack2(a.y, a.y);
        kp[p][2] = pack2(a.z, a.z);
        kp[p][3] = pack2(a.w, a.w);
        kp[p][4] = pack2(v.x, v.x);
        kp[p][5] = pack2(v.y, v.y);
        kp[p][6] = pack2(v.z, v.z);
        kp[p][7] = pack2(v.w, v.w);
        gbest[p] = CUDART_INF_F;
        gidx[p]  = 0;
    }

    // ---- software-pipelined scan: prefetch pair jp+1 before computing jp ----
    ulonglong2 c0, c1, c2, c3; u64 cmm;   // current pair row
    {
        const ulonglong2* row = reinterpret_cast<const ulonglong2*>(&spair[0][0]);
        c0 = row[0]; c1 = row[1]; c2 = row[2]; c3 = row[3];
        cmm = spair[0][8];
    }

    #pragma unroll 4
    for (int jp = 0; jp < NJP; jp++) {
        // prefetch next pair (clamped on last) -- LDS issues BEFORE the math
        const int jn = (jp + 1 < NJP) ? jp + 1 : jp;
        const ulonglong2* nrow = reinterpret_cast<const ulonglong2*>(&spair[jn][0]);
        ulonglong2 n0 = nrow[0];
        ulonglong2 n1 = nrow[1];
        ulonglong2 n2 = nrow[2];
        ulonglong2 n3 = nrow[3];
        u64 nmm = spair[jn][8];

        // compute current pair (identical op shape to R8)
        #pragma unroll
        for (int p = 0; p < KPT; p++) {
            u64 d = cmm;                  // seed = (mm_j, mm_j+1)
            d = ffma2(kp[p][0], c0.x, d);
            d = ffma2(kp[p][1], c0.y, d);
            d = ffma2(kp[p][2], c1.x, d);
            d = ffma2(kp[p][3], c1.y, d);
            d = ffma2(kp[p][4], c2.x, d);
            d = ffma2(kp[p][5], c2.y, d);
            d = ffma2(kp[p][6], c3.x, d);
            d = ffma2(kp[p][7], c3.y, d);
            float dl, dh; unpack2(d, dl, dh);
            float m = fminf(dl, dh);
            t[p] = ((jp & 3) == 0) ? m : fminf(t[p], m);
        }
        // end of group of 4 pairs (8 codes): one guarded update
        if ((jp & 3) == 3) {
            #pragma unroll
            for (int p = 0; p < KPT; p++) {
                if (t[p] < gbest[p]) { gbest[p] = t[p]; gidx[p] = jp >> 2; }
            }
        }

        // roll buffers
        c0 = n0; c1 = n1; c2 = n2; c3 = n3; cmm = nmm;
    }

    // ---- per block: recover exact first index within the winning group
    //      (c-ascending chain: bitwise identical to main loop) ----
    float4* o4 = reinterpret_cast<float4*>(out);
    #pragma unroll
    for (int p = 0; p < KPT; p++) {
        int b = base + p * TPB + tid;
        if (b >= nblocks) continue;
        const int g = gidx[p];
        const float v = gbest[p];
        int jwin = 0;
        bool found = false;
        #pragma unroll
        for (int q = 0; q < 4; q++) {
            if (found) continue;
            const int jp = g * 4 + q;
            const ulonglong2* row = reinterpret_cast<const ulonglong2*>(&spair[jp][0]);
            ulonglong2 q0 = row[0];
            ulonglong2 q1 = row[1];
            ulonglong2 q2 = row[2];
            ulonglong2 q3 = row[3];
            u64 d = spair[jp][8];
            d = ffma2(kp[p][0], q0.x, d);
            d = ffma2(kp[p][1], q0.y, d);
            d = ffma2(kp[p][2], q1.x, d);
            d = ffma2(kp[p][3], q1.y, d);
            d = ffma2(kp[p][4], q2.x, d);
            d = ffma2(kp[p][5], q2.y, d);
            d = ffma2(kp[p][6], q3.x, d);
            d = ffma2(kp[p][7], q3.y, d);
            float dl, dh; unpack2(d, dl, dh);
            if (dl == v)      { jwin = (jp << 1);     found = true; }
            else if (dh == v) { jwin = (jp << 1) + 1; found = true; }
        }
        o4[(size_t)b * 2 + 0] = sOrig[jwin][0];
        o4[(size_t)b * 2 + 1] = sOrig[jwin][1];
    }
}

extern "C" void kernel_launch(void* const* d_in, const int* in_sizes, int n_in,
                              void* d_out, int out_size)
{
    const float* x   = (const float*)d_in[0];
    const float* mem = (const float*)d_in[1];
    float* out = (float*)d_out;

    int nblocks = in_sizes[0] / MBLK;                 // 802816
    int per_cta = TPB * KPT;                          // 512
    int grid = (nblocks + per_cta - 1) / per_cta;     // 1568

    crumb_kernel<<<grid, TPB>>>(x, mem, out, nblocks);
}